// round 13
// baseline (speedup 1.0000x reference)
#include <cuda_runtime.h>
#include <math.h>
#include <stdint.h>

// ---------------- problem constants (fixed shapes) ----------------
#define TL      4
#define NB      8
#define SQ      512
#define DMODEL  1024
#define NH      16
#define DH      64
#define PAGE    16
#define PPS     80
#define CACHED_TOK 768
#define KVLEN   1280
#define NTOK    4096
#define FFND    4096
#define NUM_PAGES 640
#define QKVN    3072

// ---------------- device scratch ----------------
__device__ float    g_x[NTOK * DMODEL];
__device__ uint32_t g_xt[NTOK * DMODEL];        // tf32 copy of x
__device__ float    g_qkv[NTOK * QKVN];         // fused QKV output (fp32)
__device__ uint32_t g_attn[NTOK * DMODEL];      // attn out, tf32
__device__ float    g_tmp[NTOK * DMODEL];
__device__ uint32_t g_h[NTOK * FFND];           // FFN mid, tf32
__device__ uint32_t g_wt[50331648];             // all weights, tf32, TRANSPOSED [N][K]
__device__ float    g_bqkv[TL * QKVN];

// weight offsets inside g_wt (all [N][K])
#define WQKV_OFF 0u            // [L][3072][1024] packed Q|K|V rows
#define WO_OFF   12582912u     // [L][1024][1024]
#define W1_OFF   16777216u     // [L][4096][1024]
#define W2_OFF   33554432u     // [L][1024][4096]

// ---------------- helpers ----------------
__device__ __forceinline__ uint32_t f2tf(float x) {
    uint32_t r;
    asm("cvt.rna.tf32.f32 %0, %1;" : "=r"(r) : "f"(x));
    return r;
}

__device__ __forceinline__ void mma_tf32(float d[4],
                                         uint32_t a0, uint32_t a1, uint32_t a2, uint32_t a3,
                                         uint32_t b0, uint32_t b1) {
    asm volatile(
        "mma.sync.aligned.m16n8k8.row.col.f32.tf32.tf32.f32 "
        "{%0,%1,%2,%3}, {%4,%5,%6,%7}, {%8,%9}, {%0,%1,%2,%3};\n"
        : "+f"(d[0]), "+f"(d[1]), "+f"(d[2]), "+f"(d[3])
        : "r"(a0), "r"(a1), "r"(a2), "r"(a3), "r"(b0), "r"(b1));
}

__device__ __forceinline__ void ldsm_x4(uint32_t& r0, uint32_t& r1, uint32_t& r2, uint32_t& r3,
                                        uint32_t addr) {
    asm volatile("ldmatrix.sync.aligned.m8n8.x4.shared.b16 {%0,%1,%2,%3}, [%4];"
                 : "=r"(r0), "=r"(r1), "=r"(r2), "=r"(r3) : "r"(addr));
}

__device__ __forceinline__ void cp_async16(uint32_t smem_dst, const void* gsrc) {
    asm volatile("cp.async.ca.shared.global [%0], [%1], 16;\n" :: "r"(smem_dst), "l"(gsrc));
}
__device__ __forceinline__ void cp_commit() { asm volatile("cp.async.commit_group;\n"); }
template<int N>
__device__ __forceinline__ void cp_wait() { asm volatile("cp.async.wait_group %0;\n" :: "n"(N)); }

// ---------------- conversion / packing kernels ----------------
// transpose src[R][C] fp32 -> dst[C][R] tf32, per-layer strides, grid.z = layer
__global__ void transp_tf(const float* __restrict__ src, uint32_t* __restrict__ dst,
                          int R, int C, size_t sS, size_t sD) {
    __shared__ float t[32][33];
    src += (size_t)blockIdx.z * sS;
    dst += (size_t)blockIdx.z * sD;
    const int c0 = blockIdx.x * 32, r0 = blockIdx.y * 32;
    const int x = threadIdx.x, y = threadIdx.y;
    #pragma unroll
    for (int i = 0; i < 32; i += 8)
        t[y + i][x] = src[(size_t)(r0 + y + i) * C + c0 + x];
    __syncthreads();
    #pragma unroll
    for (int i = 0; i < 32; i += 8)
        dst[(size_t)(c0 + y + i) * R + r0 + x] = f2tf(t[x][y + i]);
}

__global__ void pack_qkv_b(const float* __restrict__ bq, const float* __restrict__ bk,
                           const float* __restrict__ bv, float* __restrict__ dst, int n) {
    int i = blockIdx.x * blockDim.x + threadIdx.x;
    if (i >= n) return;
    const int l = i / QKVN, c = i % QKVN;
    float v;
    if (c < 1024)      v = bq[l * 1024 + c];
    else if (c < 2048) v = bk[l * 1024 + c - 1024];
    else               v = bv[l * 1024 + c - 2048];
    dst[i] = v;
}

__global__ void conv_only(const float4* __restrict__ src, uint4* __restrict__ dtf, int n4) {
    int i = blockIdx.x * blockDim.x + threadIdx.x;
    if (i < n4) {
        float4 v = src[i];
        dtf[i] = make_uint4(f2tf(v.x), f2tf(v.y), f2tf(v.z), f2tf(v.w));
    }
}

// ---------------- tf32 tensor-core GEMM: ldmatrix fragments + coalesced cp.async ----
// (round-12 proven: 3883us config)
#define GSTAGES 4
#define TSTRIDE 20
#define TILE_WORDS (128 * TSTRIDE)            // 2560
#define STG_WORDS (2 * TILE_WORDS)            // 5120 words = 20KB
#define GEMM_SMEM_BYTES (GSTAGES * STG_WORDS * 4)   // 81920

template<int GELU, int OUTTF>
__launch_bounds__(256, 2)
__global__ void gemm_tc(const uint32_t* __restrict__ A, const uint32_t* __restrict__ Bt,
                        const float* __restrict__ bias,
                        float* __restrict__ Cf, uint32_t* __restrict__ Ct,
                        int M, int N, int K) {
    extern __shared__ uint32_t sm[];
    const uint32_t sbase = (uint32_t)__cvta_generic_to_shared(sm);

    const int tid  = threadIdx.x;
    const int lane = tid & 31;
    const int wid  = tid >> 5;
    const int wm   = wid & 1;
    const int wn   = wid >> 1;
    const int g    = lane >> 2;
    const int tg   = lane & 3;

    const int row0 = blockIdx.y * 128;
    const int col0 = blockIdx.x * 128;

    const int ldRow0 = (tid + 0)   >> 2, ldKq0 = (tid + 0)   & 3;
    const int ldRow1 = (tid + 256) >> 2, ldKq1 = (tid + 256) & 3;

    const uint32_t* Ap0 = A  + (size_t)(row0 + ldRow0) * K + ldKq0 * 4;
    const uint32_t* Ap1 = A  + (size_t)(row0 + ldRow1) * K + ldKq1 * 4;
    const uint32_t* Bp0 = Bt + (size_t)(col0 + ldRow0) * K + ldKq0 * 4;
    const uint32_t* Bp1 = Bt + (size_t)(col0 + ldRow1) * K + ldKq1 * 4;

    const uint32_t aOff0 = 4 * (ldRow0 * TSTRIDE + ldKq0 * 4);
    const uint32_t aOff1 = 4 * (ldRow1 * TSTRIDE + ldKq1 * 4);
    const uint32_t bOff0 = 4 * (TILE_WORDS + ldRow0 * TSTRIDE + ldKq0 * 4);
    const uint32_t bOff1 = 4 * (TILE_WORDS + ldRow1 * TSTRIDE + ldKq1 * 4);

    const int aRowL = wm * 64 + ((lane >> 3) & 1) * 8 + (lane & 7);
    const int aKL   = ((lane >> 4) & 1) * 4;
    const int bRowL = wn * 32 + ((lane >> 4) & 1) * 8 + (lane & 7);
    const int bKL   = ((lane >> 3) & 1) * 4;

    float acc[4][4][4];
    #pragma unroll
    for (int i = 0; i < 4; ++i)
        #pragma unroll
        for (int j = 0; j < 4; ++j)
            #pragma unroll
            for (int e = 0; e < 4; ++e) acc[i][j][e] = 0.f;

    const int nt = K >> 4;

    auto issue_cp = [&](int t) {
        const uint32_t sb = sbase + 4 * (t & (GSTAGES - 1)) * STG_WORDS;
        cp_async16(sb + aOff0, Ap0 + (size_t)t * 16);
        cp_async16(sb + aOff1, Ap1 + (size_t)t * 16);
        cp_async16(sb + bOff0, Bp0 + (size_t)t * 16);
        cp_async16(sb + bOff1, Bp1 + (size_t)t * 16);
    };

    #pragma unroll
    for (int s = 0; s < GSTAGES - 1; ++s) { issue_cp(s); cp_commit(); }

    for (int t = 0; t < nt; ++t) {
        cp_wait<GSTAGES - 2>();
        __syncthreads();

        const uint32_t sb  = sbase + 4 * (t & (GSTAGES - 1)) * STG_WORDS;
        const uint32_t Asb = sb;
        const uint32_t Bsb = sb + 4 * TILE_WORDS;

        #pragma unroll
        for (int ks = 0; ks < 2; ++ks) {
            const int k0 = ks * 8;
            uint32_t af[4][4], bf[4][2];
            #pragma unroll
            for (int mt = 0; mt < 4; ++mt)
                ldsm_x4(af[mt][0], af[mt][1], af[mt][2], af[mt][3],
                        Asb + 4 * ((aRowL + mt * 16) * TSTRIDE + k0 + aKL));
            #pragma unroll
            for (int op = 0; op < 2; ++op)
                ldsm_x4(bf[2 * op][0], bf[2 * op][1], bf[2 * op + 1][0], bf[2 * op + 1][1],
                        Bsb + 4 * ((bRowL + op * 16) * TSTRIDE + k0 + bKL));
            #pragma unroll
            for (int mt = 0; mt < 4; ++mt)
                #pragma unroll
                for (int j = 0; j < 4; ++j)
                    mma_tf32(acc[mt][j], af[mt][0], af[mt][1], af[mt][2], af[mt][3],
                             bf[j][0], bf[j][1]);
        }

        if (t + GSTAGES - 1 < nt) issue_cp(t + GSTAGES - 1);
        cp_commit();
    }

    #pragma unroll
    for (int j = 0; j < 4; ++j) {
        const int col = col0 + wn * 32 + j * 8 + 2 * tg;
        const float2 bb = *(const float2*)(bias + col);
        #pragma unroll
        for (int mt = 0; mt < 4; ++mt) {
            const int row = row0 + wm * 64 + mt * 16 + g;
            float2 lo, hi;
            lo.x = acc[mt][j][0] + bb.x;
            lo.y = acc[mt][j][1] + bb.y;
            hi.x = acc[mt][j][2] + bb.x;
            hi.y = acc[mt][j][3] + bb.y;
            if (GELU) {
                lo.x *= normcdff(lo.x); lo.y *= normcdff(lo.y);
                hi.x *= normcdff(hi.x); hi.y *= normcdff(hi.y);
            }
            if (OUTTF) {
                *(uint2*)(Ct + (size_t)row * N + col)       = make_uint2(f2tf(lo.x), f2tf(lo.y));
                *(uint2*)(Ct + (size_t)(row + 8) * N + col) = make_uint2(f2tf(hi.x), f2tf(hi.y));
            } else {
                *(float2*)(Cf + (size_t)row * N + col)       = lo;
                *(float2*)(Cf + (size_t)(row + 8) * N + col) = hi;
            }
        }
    }
}

// ---------------- tensor-core paged-KV flash attention ----------------
// Round-7 double-buffered structure, but OCCUPANCY 2: 2 x 108.5KB = 217KB fits
// the 227KB sm_103a carveout; 16 warps/SM hide KV-gather latency cross-CTA.
#define AT_KVW (64 * 72)
#define AT_PSW (16 * 68)
#define ATTN_SMEM_BYTES ((4 * AT_KVW + 8 * AT_PSW) * 4)   // 108544

__launch_bounds__(256, 2)
__global__ void attn_tc(const float* __restrict__ qkv, const float* __restrict__ ptab,
                        const int* __restrict__ kvidx, uint32_t* __restrict__ out) {
    extern __shared__ uint32_t smA[];
    uint32_t* KtB = smA;                        // [2][64][72], swizzled [d][j]
    uint32_t* VtB = smA + 2 * AT_KVW;           // [2][64][72], [j][d]
    const int tid  = threadIdx.x;
    const int lane = tid & 31;
    const int wid  = tid >> 5;
    const int g    = lane >> 2;
    const int tg   = lane & 3;
    uint32_t* Ps = smA + 4 * AT_KVW + wid * AT_PSW;

    const int qt = blockIdx.x, h = blockIdx.y, b = blockIdx.z;
    const int row0 = qt * 128 + wid * 16;
    const float scale = 0.125f;

    uint32_t qf[8][4];
    {
        const float* q0 = qkv + (size_t)(b * SQ + row0 + g) * QKVN + h * DH;
        const float* q1 = q0 + 8 * QKVN;
        #pragma unroll
        for (int s = 0; s < 8; ++s) {
            qf[s][0] = f2tf(q0[8 * s + tg] * scale);
            qf[s][1] = f2tf(q1[8 * s + tg] * scale);
            qf[s][2] = f2tf(q0[8 * s + tg + 4] * scale);
            qf[s][3] = f2tf(q1[8 * s + tg + 4] * scale);
        }
    }

    float o[8][4];
    #pragma unroll
    for (int da = 0; da < 8; ++da)
        #pragma unroll
        for (int e = 0; e < 4; ++e) o[da][e] = 0.f;
    float m0 = -1e30f, m1 = -1e30f, l0 = 0.f, l1 = 0.f;

    float4 kst[4], vst[4];
    auto ldtile = [&](int kt) {
        #pragma unroll
        for (int r = 0; r < 4; ++r) {
            int c = tid + r * 256;
            int tok = c >> 4;
            int d4  = (c & 15) << 2;
            int kv = kt * 64 + tok;
            const float *kp, *vp;
            if (kv < CACHED_TOK) {
                int page = kvidx[b * PPS + (kv >> 4)];
                size_t base = (size_t)page * (2 * PAGE * NH * DH)
                            + (size_t)(kv & 15) * (NH * DH) + h * DH + d4;
                kp = ptab + base;
                vp = ptab + base + PAGE * NH * DH;
            } else {
                size_t off = (size_t)(b * SQ + (kv - CACHED_TOK)) * QKVN + h * DH + d4;
                kp = qkv + off + DMODEL;
                vp = qkv + off + 2 * DMODEL;
            }
            kst[r] = *(const float4*)kp;
            vst[r] = *(const float4*)vp;
        }
    };
    auto sttile = [&](int buf) {
        uint32_t* Kb = KtB + buf * AT_KVW;
        uint32_t* Vb = VtB + buf * AT_KVW;
        #pragma unroll
        for (int r = 0; r < 4; ++r) {
            int c = tid + r * 256;
            int tok = c >> 4;
            int d4  = (c & 15) << 2;
            int colp = tok ^ d4;
            Kb[(d4 + 0) * 72 + colp] = f2tf(kst[r].x);
            Kb[(d4 + 1) * 72 + colp] = f2tf(kst[r].y);
            Kb[(d4 + 2) * 72 + colp] = f2tf(kst[r].z);
            Kb[(d4 + 3) * 72 + colp] = f2tf(kst[r].w);
            *(uint4*)&Vb[tok * 72 + d4] =
                make_uint4(f2tf(vst[r].x), f2tf(vst[r].y), f2tf(vst[r].z), f2tf(vst[r].w));
        }
    };

    ldtile(0);
    sttile(0);
    __syncthreads();

    int buf = 0;
    for (int kt = 0; kt < KVLEN / 64; ++kt) {
        if (kt + 1 < KVLEN / 64) ldtile(kt + 1);

        const uint32_t* Kb = KtB + buf * AT_KVW;
        float sc[8][4];
        #pragma unroll
        for (int a = 0; a < 8; ++a)
            #pragma unroll
            for (int e = 0; e < 4; ++e) sc[a][e] = 0.f;
        #pragma unroll
        for (int s = 0; s < 8; ++s) {
            const uint32_t a0 = qf[s][0], a1 = qf[s][1], a2 = qf[s][2], a3 = qf[s][3];
            const int rk0 = (8 * s + tg) * 72;
            const int rk1 = (8 * s + tg + 4) * 72;
            #pragma unroll
            for (int a = 0; a < 8; ++a) {
                uint32_t b0 = Kb[rk0 + (8 * (a ^ s) + g)];
                uint32_t b1 = Kb[rk1 + (8 * (a ^ s) + (g ^ 4))];
                mma_tf32(sc[a], a0, a1, a2, a3, b0, b1);
            }
        }

        float mx0 = -1e30f, mx1 = -1e30f;
        #pragma unroll
        for (int a = 0; a < 8; ++a) {
            mx0 = fmaxf(mx0, fmaxf(sc[a][0], sc[a][1]));
            mx1 = fmaxf(mx1, fmaxf(sc[a][2], sc[a][3]));
        }
        mx0 = fmaxf(mx0, __shfl_xor_sync(0xffffffffu, mx0, 1));
        mx0 = fmaxf(mx0, __shfl_xor_sync(0xffffffffu, mx0, 2));
        mx1 = fmaxf(mx1, __shfl_xor_sync(0xffffffffu, mx1, 1));
        mx1 = fmaxf(mx1, __shfl_xor_sync(0xffffffffu, mx1, 2));
        const float mn0 = fmaxf(m0, mx0), mn1 = fmaxf(m1, mx1);
        const float c0 = __expf(m0 - mn0), c1 = __expf(m1 - mn1);
        float s0 = 0.f, s1 = 0.f;
        #pragma unroll
        for (int a = 0; a < 8; ++a) {
            sc[a][0] = __expf(sc[a][0] - mn0); s0 += sc[a][0];
            sc[a][1] = __expf(sc[a][1] - mn0); s0 += sc[a][1];
            sc[a][2] = __expf(sc[a][2] - mn1); s1 += sc[a][2];
            sc[a][3] = __expf(sc[a][3] - mn1); s1 += sc[a][3];
        }
        s0 += __shfl_xor_sync(0xffffffffu, s0, 1);
        s0 += __shfl_xor_sync(0xffffffffu, s0, 2);
        s1 += __shfl_xor_sync(0xffffffffu, s1, 1);
        s1 += __shfl_xor_sync(0xffffffffu, s1, 2);
        l0 = l0 * c0 + s0;  l1 = l1 * c1 + s1;
        m0 = mn0;  m1 = mn1;
        #pragma unroll
        for (int da = 0; da < 8; ++da) {
            o[da][0] *= c0; o[da][1] *= c0;
            o[da][2] *= c1; o[da][3] *= c1;
        }

        #pragma unroll
        for (int a = 0; a < 8; ++a) {
            const int cb = 8 * a + 2 * tg;
            Ps[g * 68 + cb]           = f2tf(sc[a][0]);
            Ps[g * 68 + cb + 1]       = f2tf(sc[a][1]);
            Ps[(g + 8) * 68 + cb]     = f2tf(sc[a][2]);
            Ps[(g + 8) * 68 + cb + 1] = f2tf(sc[a][3]);
        }
        __syncwarp();

        const uint32_t* Vb = VtB + buf * AT_KVW;
        #pragma unroll
        for (int s = 0; s < 8; ++s) {
            uint32_t a0 = Ps[g * 68 + 8 * s + tg];
            uint32_t a1 = Ps[(g + 8) * 68 + 8 * s + tg];
            uint32_t a2 = Ps[g * 68 + 8 * s + tg + 4];
            uint32_t a3 = Ps[(g + 8) * 68 + 8 * s + tg + 4];
            const int rk0 = (8 * s + tg) * 72;
            const int rk1 = (8 * s + tg + 4) * 72;
            #pragma unroll
            for (int da = 0; da < 8; ++da) {
                uint32_t b0 = Vb[rk0 + 8 * da + g];
                uint32_t b1 = Vb[rk1 + 8 * da + g];
                mma_tf32(o[da], a0, a1, a2, a3, b0, b1);
            }
        }

        if (kt + 1 < KVLEN / 64) {
            sttile(buf ^ 1);
            __syncthreads();
            buf ^= 1;
        }
    }

    const float inv0 = 1.f / l0, inv1 = 1.f / l1;
    uint32_t* o0 = out + (size_t)(b * SQ + row0 + g) * DMODEL + h * DH;
    uint32_t* o1 = o0 + 8 * DMODEL;
    #pragma unroll
    for (int da = 0; da < 8; ++da) {
        const int col = 8 * da + 2 * tg;
        *(uint2*)&o0[col] = make_uint2(f2tf(o[da][0] * inv0), f2tf(o[da][1] * inv0));
        *(uint2*)&o1[col] = make_uint2(f2tf(o[da][2] * inv1), f2tf(o[da][3] * inv1));
    }
}

// ---------------- fused residual-add + LayerNorm (fp32 + tf32 outputs) ----------------
__launch_bounds__(256)
__global__ void ln_kernel(const float* __restrict__ resid, const float* __restrict__ y,
                          const float* __restrict__ gg, const float* __restrict__ bb,
                          float* __restrict__ outf, uint32_t* __restrict__ outt) {
    const int row = blockIdx.x, tid = threadIdx.x;
    __shared__ float redS[8], redS2[8];
    float4 rv = *(const float4*)(resid + (size_t)row * DMODEL + tid * 4);
    float4 yv = *(const float4*)(y     + (size_t)row * DMODEL + tid * 4);
    float v0 = rv.x + yv.x, v1 = rv.y + yv.y, v2 = rv.z + yv.z, v3 = rv.w + yv.w;
    float s  = v0 + v1 + v2 + v3;
    float s2 = v0 * v0 + v1 * v1 + v2 * v2 + v3 * v3;
    #pragma unroll
    for (int o = 16; o > 0; o >>= 1) {
        s  += __shfl_xor_sync(0xffffffffu, s,  o);
        s2 += __shfl_xor_sync(0xffffffffu, s2, o);
    }
    if ((tid & 31) == 0) { redS[tid >> 5] = s; redS2[tid >> 5] = s2; }
    __syncthreads();
    if (tid < 32) {
        float a  = (tid < 8) ? redS[tid]  : 0.f;
        float a2 = (tid < 8) ? redS2[tid] : 0.f;
        #pragma unroll
        for (int o = 4; o > 0; o >>= 1) {
            a  += __shfl_xor_sync(0xffffffffu, a,  o);
            a2 += __shfl_xor_sync(0xffffffffu, a2, o);
        }
        if (tid == 0) { redS[0] = a; redS2[0] = a2; }
    }
    __syncthreads();
    const float mean = redS[0] * (1.f / DMODEL);
    const float var  = redS2[0] * (1.f / DMODEL) - mean * mean;
    const float inv  = rsqrtf(var + 1e-5f);
    float4 gv = *(const float4*)(gg + tid * 4);
    float4 bv = *(const float4*)(bb + tid * 4);
    float4 o;
    o.x = (v0 - mean) * inv * gv.x + bv.x;
    o.y = (v1 - mean) * inv * gv.y + bv.y;
    o.z = (v2 - mean) * inv * gv.z + bv.z;
    o.w = (v3 - mean) * inv * gv.w + bv.w;
    *(float4*)(outf + (size_t)row * DMODEL + tid * 4) = o;
    *(uint4*)(outt + (size_t)row * DMODEL + tid * 4) =
        make_uint4(f2tf(o.x), f2tf(o.y), f2tf(o.z), f2tf(o.w));
}

// ---------------- launcher ----------------
extern "C" void kernel_launch(void* const* d_in, const int* in_sizes, int n_in,
                              void* d_out, int out_size) {
    const float* x      = (const float*)d_in[0];
    const int*   kvidx  = (const int*)d_in[3];
    const float* ptab   = (const float*)d_in[5];
    const float* Wq = (const float*)d_in[6];
    const float* bq = (const float*)d_in[7];
    const float* Wk = (const float*)d_in[8];
    const float* bk = (const float*)d_in[9];
    const float* Wv = (const float*)d_in[10];
    const float* bv = (const float*)d_in[11];
    const float* Wo = (const float*)d_in[12];
    const float* bo = (const float*)d_in[13];
    const float* ln1g = (const float*)d_in[14];
    const float* ln1b = (const float*)d_in[15];
    const float* W1 = (const float*)d_in[16];
    const float* b1 = (const float*)d_in[17];
    const float* W2 = (const float*)d_in[18];
    const float* b2 = (const float*)d_in[19];
    const float* ln2g = (const float*)d_in[20];
    const float* ln2b = (const float*)d_in[21];

    float *gx, *gqkv, *gt, *gbqkv;
    uint32_t *gxt, *ga, *gh, *gwt;
    cudaGetSymbolAddress((void**)&gx,    g_x);
    cudaGetSymbolAddress((void**)&gxt,   g_xt);
    cudaGetSymbolAddress((void**)&gqkv,  g_qkv);
    cudaGetSymbolAddress((void**)&ga,    g_attn);
    cudaGetSymbolAddress((void**)&gt,    g_tmp);
    cudaGetSymbolAddress((void**)&gh,    g_h);
    cudaGetSymbolAddress((void**)&gwt,   g_wt);
    cudaGetSymbolAddress((void**)&gbqkv, g_bqkv);

    cudaFuncSetAttribute((const void*)attn_tc,
                         cudaFuncAttributeMaxDynamicSharedMemorySize, ATTN_SMEM_BYTES);
    cudaFuncSetAttribute((const void*)gemm_tc<0, 0>,
                         cudaFuncAttributeMaxDynamicSharedMemorySize, GEMM_SMEM_BYTES);
    cudaFuncSetAttribute((const void*)gemm_tc<1, 1>,
                         cudaFuncAttributeMaxDynamicSharedMemorySize, GEMM_SMEM_BYTES);

    // ---- weight transpose+convert to [N][K] tf32 (once per call) ----
    {
        dim3 blk(32, 8);
        transp_tf<<<dim3(32, 32, TL), blk>>>(Wq, gwt + WQKV_OFF,
                                             1024, 1024, (size_t)1048576, (size_t)3145728);
        transp_tf<<<dim3(32, 32, TL), blk>>>(Wk, gwt + WQKV_OFF + 1024 * 1024,
                                             1024, 1024, (size_t)1048576, (size_t)3145728);
        transp_tf<<<dim3(32, 32, TL), blk>>>(Wv, gwt + WQKV_OFF + 2048 * 1024,
                                             1024, 1024, (size_t)1048576, (size_t)3145728);
        transp_tf<<<dim3(32, 32, TL), blk>>>(Wo, gwt + WO_OFF,
                                             1024, 1024, (size_t)1048576, (size_t)1048576);
        transp_tf<<<dim3(128, 32, TL), blk>>>(W1, gwt + W1_OFF,
                                              1024, 4096, (size_t)4194304, (size_t)4194304);
        transp_tf<<<dim3(32, 128, TL), blk>>>(W2, gwt + W2_OFF,
                                              4096, 1024, (size_t)4194304, (size_t)4194304);
        pack_qkv_b<<<(TL * QKVN + 255) / 256, 256>>>(bq, bk, bv, gbqkv, TL * QKVN);
    }

    const int n4 = NTOK * DMODEL / 4;
    conv_only<<<(n4 + 255) / 256, 256>>>((const float4*)x, (uint4*)gxt, n4);

    dim3 gQKV(QKVN / 128, NTOK / 128);     // (24, 32)
    dim3 gProj(DMODEL / 128, NTOK / 128);  // (8, 32)
    dim3 gF1(FFND / 128, NTOK / 128);      // (32, 32)
    dim3 gAttn(SQ / 128, NH, NB);          // (4, 16, 8)

    for (int l = 0; l < TL; ++l) {
        const uint32_t* Wqkv_l = gwt + WQKV_OFF + (size_t)l * DMODEL * QKVN;
        const uint32_t* Wo_l   = gwt + WO_OFF + (size_t)l * DMODEL * DMODEL;
        const uint32_t* W1_l   = gwt + W1_OFF + (size_t)l * DMODEL * FFND;
        const uint32_t* W2_l   = gwt + W2_OFF + (size_t)l * FFND * DMODEL;
        const float* ptab_l = ptab + (size_t)l * NUM_PAGES * 2 * PAGE * NH * DH;

        gemm_tc<0, 0><<<gQKV, 256, GEMM_SMEM_BYTES>>>(gxt, Wqkv_l, gbqkv + l * QKVN,
                                                      gqkv, nullptr, NTOK, QKVN, DMODEL);

        attn_tc<<<gAttn, 256, ATTN_SMEM_BYTES>>>(gqkv, ptab_l, kvidx, ga);

        gemm_tc<0, 0><<<gProj, 256, GEMM_SMEM_BYTES>>>(ga, Wo_l, bo + l * DMODEL,
                                                       gt, nullptr, NTOK, DMODEL, DMODEL);
        // layer-0 residual comes straight from the input tensor
        const float* resid1 = (l == 0) ? x : gx;
        ln_kernel<<<NTOK, 256>>>(resid1, gt, ln1g + l * DMODEL, ln1b + l * DMODEL, gx, gxt);

        gemm_tc<1, 1><<<gF1, 256, GEMM_SMEM_BYTES>>>(gxt, W1_l, b1 + l * FFND,
                                                     nullptr, gh, NTOK, FFND, DMODEL);
        gemm_tc<0, 0><<<gProj, 256, GEMM_SMEM_BYTES>>>(gh, W2_l, b2 + l * DMODEL,
                                                       gt, nullptr, NTOK, DMODEL, FFND);

        float* lnOut = (l == TL - 1) ? (float*)d_out : gx;
        ln_kernel<<<NTOK, 256>>>(gx, gt, ln2g + l * DMODEL, ln2b + l * DMODEL, lnOut, gxt);
    }
}

// round 14
// speedup vs baseline: 1.0454x; 1.0454x over previous
#include <cuda_runtime.h>
#include <math.h>
#include <stdint.h>

// ---------------- problem constants (fixed shapes) ----------------
#define TL      4
#define NB      8
#define SQ      512
#define DMODEL  1024
#define NH      16
#define DH      64
#define PAGE    16
#define PPS     80
#define CACHED_TOK 768
#define KVLEN   1280
#define NTOK    4096
#define FFND    4096
#define NUM_PAGES 640
#define QKVN    3072

// ---------------- device scratch ----------------
__device__ float    g_x[NTOK * DMODEL];
__device__ uint32_t g_xt[NTOK * DMODEL];        // tf32 copy of x
__device__ float    g_qkv[NTOK * QKVN];         // fused QKV output (fp32)
__device__ uint32_t g_attn[NTOK * DMODEL];      // attn out, tf32
__device__ float    g_tmp[NTOK * DMODEL];
__device__ uint32_t g_h[NTOK * FFND];           // FFN mid, tf32
__device__ uint32_t g_wt[50331648];             // all weights, tf32, TRANSPOSED [N][K]
__device__ float    g_bqkv[TL * QKVN];

// weight offsets inside g_wt (all [N][K])
#define WQKV_OFF 0u            // [L][3072][1024] packed Q|K|V rows
#define WO_OFF   12582912u     // [L][1024][1024]
#define W1_OFF   16777216u     // [L][4096][1024]
#define W2_OFF   33554432u     // [L][1024][4096]

// ---------------- helpers ----------------
__device__ __forceinline__ uint32_t f2tf(float x) {
    uint32_t r;
    asm("cvt.rna.tf32.f32 %0, %1;" : "=r"(r) : "f"(x));
    return r;
}

__device__ __forceinline__ void mma_tf32(float d[4],
                                         uint32_t a0, uint32_t a1, uint32_t a2, uint32_t a3,
                                         uint32_t b0, uint32_t b1) {
    asm volatile(
        "mma.sync.aligned.m16n8k8.row.col.f32.tf32.tf32.f32 "
        "{%0,%1,%2,%3}, {%4,%5,%6,%7}, {%8,%9}, {%0,%1,%2,%3};\n"
        : "+f"(d[0]), "+f"(d[1]), "+f"(d[2]), "+f"(d[3])
        : "r"(a0), "r"(a1), "r"(a2), "r"(a3), "r"(b0), "r"(b1));
}

__device__ __forceinline__ void ldsm_x4(uint32_t& r0, uint32_t& r1, uint32_t& r2, uint32_t& r3,
                                        uint32_t addr) {
    asm volatile("ldmatrix.sync.aligned.m8n8.x4.shared.b16 {%0,%1,%2,%3}, [%4];"
                 : "=r"(r0), "=r"(r1), "=r"(r2), "=r"(r3) : "r"(addr));
}

__device__ __forceinline__ void cp_async16(uint32_t smem_dst, const void* gsrc) {
    asm volatile("cp.async.ca.shared.global [%0], [%1], 16;\n" :: "r"(smem_dst), "l"(gsrc));
}
__device__ __forceinline__ void cp_commit() { asm volatile("cp.async.commit_group;\n"); }
template<int N>
__device__ __forceinline__ void cp_wait() { asm volatile("cp.async.wait_group %0;\n" :: "n"(N)); }

// ---------------- conversion / packing kernels ----------------
// transpose src[R][C] fp32 -> dst[C][R] tf32, per-layer strides, grid.z = layer
__global__ void transp_tf(const float* __restrict__ src, uint32_t* __restrict__ dst,
                          int R, int C, size_t sS, size_t sD) {
    __shared__ float t[32][33];
    src += (size_t)blockIdx.z * sS;
    dst += (size_t)blockIdx.z * sD;
    const int c0 = blockIdx.x * 32, r0 = blockIdx.y * 32;
    const int x = threadIdx.x, y = threadIdx.y;
    #pragma unroll
    for (int i = 0; i < 32; i += 8)
        t[y + i][x] = src[(size_t)(r0 + y + i) * C + c0 + x];
    __syncthreads();
    #pragma unroll
    for (int i = 0; i < 32; i += 8)
        dst[(size_t)(c0 + y + i) * R + r0 + x] = f2tf(t[x][y + i]);
}

__global__ void pack_qkv_b(const float* __restrict__ bq, const float* __restrict__ bk,
                           const float* __restrict__ bv, float* __restrict__ dst, int n) {
    int i = blockIdx.x * blockDim.x + threadIdx.x;
    if (i >= n) return;
    const int l = i / QKVN, c = i % QKVN;
    float v;
    if (c < 1024)      v = bq[l * 1024 + c];
    else if (c < 2048) v = bk[l * 1024 + c - 1024];
    else               v = bv[l * 1024 + c - 2048];
    dst[i] = v;
}

__global__ void conv_only(const float4* __restrict__ src, uint4* __restrict__ dtf, int n4) {
    int i = blockIdx.x * blockDim.x + threadIdx.x;
    if (i < n4) {
        float4 v = src[i];
        dtf[i] = make_uint4(f2tf(v.x), f2tf(v.y), f2tf(v.z), f2tf(v.w));
    }
}

// ---------------- tf32 tensor-core GEMM: ldmatrix fragments + coalesced cp.async ----
// (round-12 proven: 3883us config)
#define GSTAGES 4
#define TSTRIDE 20
#define TILE_WORDS (128 * TSTRIDE)            // 2560
#define STG_WORDS (2 * TILE_WORDS)            // 5120 words = 20KB
#define GEMM_SMEM_BYTES (GSTAGES * STG_WORDS * 4)   // 81920

template<int GELU, int OUTTF>
__launch_bounds__(256, 2)
__global__ void gemm_tc(const uint32_t* __restrict__ A, const uint32_t* __restrict__ Bt,
                        const float* __restrict__ bias,
                        float* __restrict__ Cf, uint32_t* __restrict__ Ct,
                        int M, int N, int K) {
    extern __shared__ uint32_t sm[];
    const uint32_t sbase = (uint32_t)__cvta_generic_to_shared(sm);

    const int tid  = threadIdx.x;
    const int lane = tid & 31;
    const int wid  = tid >> 5;
    const int wm   = wid & 1;
    const int wn   = wid >> 1;
    const int g    = lane >> 2;
    const int tg   = lane & 3;

    const int row0 = blockIdx.y * 128;
    const int col0 = blockIdx.x * 128;

    const int ldRow0 = (tid + 0)   >> 2, ldKq0 = (tid + 0)   & 3;
    const int ldRow1 = (tid + 256) >> 2, ldKq1 = (tid + 256) & 3;

    const uint32_t* Ap0 = A  + (size_t)(row0 + ldRow0) * K + ldKq0 * 4;
    const uint32_t* Ap1 = A  + (size_t)(row0 + ldRow1) * K + ldKq1 * 4;
    const uint32_t* Bp0 = Bt + (size_t)(col0 + ldRow0) * K + ldKq0 * 4;
    const uint32_t* Bp1 = Bt + (size_t)(col0 + ldRow1) * K + ldKq1 * 4;

    const uint32_t aOff0 = 4 * (ldRow0 * TSTRIDE + ldKq0 * 4);
    const uint32_t aOff1 = 4 * (ldRow1 * TSTRIDE + ldKq1 * 4);
    const uint32_t bOff0 = 4 * (TILE_WORDS + ldRow0 * TSTRIDE + ldKq0 * 4);
    const uint32_t bOff1 = 4 * (TILE_WORDS + ldRow1 * TSTRIDE + ldKq1 * 4);

    const int aRowL = wm * 64 + ((lane >> 3) & 1) * 8 + (lane & 7);
    const int aKL   = ((lane >> 4) & 1) * 4;
    const int bRowL = wn * 32 + ((lane >> 4) & 1) * 8 + (lane & 7);
    const int bKL   = ((lane >> 3) & 1) * 4;

    float acc[4][4][4];
    #pragma unroll
    for (int i = 0; i < 4; ++i)
        #pragma unroll
        for (int j = 0; j < 4; ++j)
            #pragma unroll
            for (int e = 0; e < 4; ++e) acc[i][j][e] = 0.f;

    const int nt = K >> 4;

    auto issue_cp = [&](int t) {
        const uint32_t sb = sbase + 4 * (t & (GSTAGES - 1)) * STG_WORDS;
        cp_async16(sb + aOff0, Ap0 + (size_t)t * 16);
        cp_async16(sb + aOff1, Ap1 + (size_t)t * 16);
        cp_async16(sb + bOff0, Bp0 + (size_t)t * 16);
        cp_async16(sb + bOff1, Bp1 + (size_t)t * 16);
    };

    #pragma unroll
    for (int s = 0; s < GSTAGES - 1; ++s) { issue_cp(s); cp_commit(); }

    for (int t = 0; t < nt; ++t) {
        cp_wait<GSTAGES - 2>();
        __syncthreads();

        const uint32_t sb  = sbase + 4 * (t & (GSTAGES - 1)) * STG_WORDS;
        const uint32_t Asb = sb;
        const uint32_t Bsb = sb + 4 * TILE_WORDS;

        #pragma unroll
        for (int ks = 0; ks < 2; ++ks) {
            const int k0 = ks * 8;
            uint32_t af[4][4], bf[4][2];
            #pragma unroll
            for (int mt = 0; mt < 4; ++mt)
                ldsm_x4(af[mt][0], af[mt][1], af[mt][2], af[mt][3],
                        Asb + 4 * ((aRowL + mt * 16) * TSTRIDE + k0 + aKL));
            #pragma unroll
            for (int op = 0; op < 2; ++op)
                ldsm_x4(bf[2 * op][0], bf[2 * op][1], bf[2 * op + 1][0], bf[2 * op + 1][1],
                        Bsb + 4 * ((bRowL + op * 16) * TSTRIDE + k0 + bKL));
            #pragma unroll
            for (int mt = 0; mt < 4; ++mt)
                #pragma unroll
                for (int j = 0; j < 4; ++j)
                    mma_tf32(acc[mt][j], af[mt][0], af[mt][1], af[mt][2], af[mt][3],
                             bf[j][0], bf[j][1]);
        }

        if (t + GSTAGES - 1 < nt) issue_cp(t + GSTAGES - 1);
        cp_commit();
    }

    #pragma unroll
    for (int j = 0; j < 4; ++j) {
        const int col = col0 + wn * 32 + j * 8 + 2 * tg;
        const float2 bb = *(const float2*)(bias + col);
        #pragma unroll
        for (int mt = 0; mt < 4; ++mt) {
            const int row = row0 + wm * 64 + mt * 16 + g;
            float2 lo, hi;
            lo.x = acc[mt][j][0] + bb.x;
            lo.y = acc[mt][j][1] + bb.y;
            hi.x = acc[mt][j][2] + bb.x;
            hi.y = acc[mt][j][3] + bb.y;
            if (GELU) {
                lo.x *= normcdff(lo.x); lo.y *= normcdff(lo.y);
                hi.x *= normcdff(hi.x); hi.y *= normcdff(hi.y);
            }
            if (OUTTF) {
                *(uint2*)(Ct + (size_t)row * N + col)       = make_uint2(f2tf(lo.x), f2tf(lo.y));
                *(uint2*)(Ct + (size_t)(row + 8) * N + col) = make_uint2(f2tf(hi.x), f2tf(hi.y));
            } else {
                *(float2*)(Cf + (size_t)row * N + col)       = lo;
                *(float2*)(Cf + (size_t)(row + 8) * N + col) = hi;
            }
        }
    }
}

// ---------------- tensor-core paged-KV flash attention (round-12 proven: occ 1) ----------------
#define AT_KVW (64 * 72)
#define AT_PSW (16 * 68)
#define ATTN_SMEM_BYTES ((4 * AT_KVW + 8 * AT_PSW) * 4)   // 108544

__launch_bounds__(256, 1)
__global__ void attn_tc(const float* __restrict__ qkv, const float* __restrict__ ptab,
                        const int* __restrict__ kvidx, uint32_t* __restrict__ out) {
    extern __shared__ uint32_t smA[];
    uint32_t* KtB = smA;                        // [2][64][72], swizzled [d][j]
    uint32_t* VtB = smA + 2 * AT_KVW;           // [2][64][72], [j][d]
    const int tid  = threadIdx.x;
    const int lane = tid & 31;
    const int wid  = tid >> 5;
    const int g    = lane >> 2;
    const int tg   = lane & 3;
    uint32_t* Ps = smA + 4 * AT_KVW + wid * AT_PSW;

    const int qt = blockIdx.x, h = blockIdx.y, b = blockIdx.z;
    const int row0 = qt * 128 + wid * 16;
    const float scale = 0.125f;

    uint32_t qf[8][4];
    {
        const float* q0 = qkv + (size_t)(b * SQ + row0 + g) * QKVN + h * DH;
        const float* q1 = q0 + 8 * QKVN;
        #pragma unroll
        for (int s = 0; s < 8; ++s) {
            qf[s][0] = f2tf(q0[8 * s + tg] * scale);
            qf[s][1] = f2tf(q1[8 * s + tg] * scale);
            qf[s][2] = f2tf(q0[8 * s + tg + 4] * scale);
            qf[s][3] = f2tf(q1[8 * s + tg + 4] * scale);
        }
    }

    float o[8][4];
    #pragma unroll
    for (int da = 0; da < 8; ++da)
        #pragma unroll
        for (int e = 0; e < 4; ++e) o[da][e] = 0.f;
    float m0 = -1e30f, m1 = -1e30f, l0 = 0.f, l1 = 0.f;

    float4 kst[4], vst[4];
    auto ldtile = [&](int kt) {
        #pragma unroll
        for (int r = 0; r < 4; ++r) {
            int c = tid + r * 256;
            int tok = c >> 4;
            int d4  = (c & 15) << 2;
            int kv = kt * 64 + tok;
            const float *kp, *vp;
            if (kv < CACHED_TOK) {
                int page = kvidx[b * PPS + (kv >> 4)];
                size_t base = (size_t)page * (2 * PAGE * NH * DH)
                            + (size_t)(kv & 15) * (NH * DH) + h * DH + d4;
                kp = ptab + base;
                vp = ptab + base + PAGE * NH * DH;
            } else {
                size_t off = (size_t)(b * SQ + (kv - CACHED_TOK)) * QKVN + h * DH + d4;
                kp = qkv + off + DMODEL;
                vp = qkv + off + 2 * DMODEL;
            }
            kst[r] = *(const float4*)kp;
            vst[r] = *(const float4*)vp;
        }
    };
    auto sttile = [&](int buf) {
        uint32_t* Kb = KtB + buf * AT_KVW;
        uint32_t* Vb = VtB + buf * AT_KVW;
        #pragma unroll
        for (int r = 0; r < 4; ++r) {
            int c = tid + r * 256;
            int tok = c >> 4;
            int d4  = (c & 15) << 2;
            int colp = tok ^ d4;
            Kb[(d4 + 0) * 72 + colp] = f2tf(kst[r].x);
            Kb[(d4 + 1) * 72 + colp] = f2tf(kst[r].y);
            Kb[(d4 + 2) * 72 + colp] = f2tf(kst[r].z);
            Kb[(d4 + 3) * 72 + colp] = f2tf(kst[r].w);
            *(uint4*)&Vb[tok * 72 + d4] =
                make_uint4(f2tf(vst[r].x), f2tf(vst[r].y), f2tf(vst[r].z), f2tf(vst[r].w));
        }
    };

    ldtile(0);
    sttile(0);
    __syncthreads();

    int buf = 0;
    for (int kt = 0; kt < KVLEN / 64; ++kt) {
        if (kt + 1 < KVLEN / 64) ldtile(kt + 1);

        const uint32_t* Kb = KtB + buf * AT_KVW;
        float sc[8][4];
        #pragma unroll
        for (int a = 0; a < 8; ++a)
            #pragma unroll
            for (int e = 0; e < 4; ++e) sc[a][e] = 0.f;
        #pragma unroll
        for (int s = 0; s < 8; ++s) {
            const uint32_t a0 = qf[s][0], a1 = qf[s][1], a2 = qf[s][2], a3 = qf[s][3];
            const int rk0 = (8 * s + tg) * 72;
            const int rk1 = (8 * s + tg + 4) * 72;
            #pragma unroll
            for (int a = 0; a < 8; ++a) {
                uint32_t b0 = Kb[rk0 + (8 * (a ^ s) + g)];
                uint32_t b1 = Kb[rk1 + (8 * (a ^ s) + (g ^ 4))];
                mma_tf32(sc[a], a0, a1, a2, a3, b0, b1);
            }
        }

        float mx0 = -1e30f, mx1 = -1e30f;
        #pragma unroll
        for (int a = 0; a < 8; ++a) {
            mx0 = fmaxf(mx0, fmaxf(sc[a][0], sc[a][1]));
            mx1 = fmaxf(mx1, fmaxf(sc[a][2], sc[a][3]));
        }
        mx0 = fmaxf(mx0, __shfl_xor_sync(0xffffffffu, mx0, 1));
        mx0 = fmaxf(mx0, __shfl_xor_sync(0xffffffffu, mx0, 2));
        mx1 = fmaxf(mx1, __shfl_xor_sync(0xffffffffu, mx1, 1));
        mx1 = fmaxf(mx1, __shfl_xor_sync(0xffffffffu, mx1, 2));
        const float mn0 = fmaxf(m0, mx0), mn1 = fmaxf(m1, mx1);
        const float c0 = __expf(m0 - mn0), c1 = __expf(m1 - mn1);
        float s0 = 0.f, s1 = 0.f;
        #pragma unroll
        for (int a = 0; a < 8; ++a) {
            sc[a][0] = __expf(sc[a][0] - mn0); s0 += sc[a][0];
            sc[a][1] = __expf(sc[a][1] - mn0); s0 += sc[a][1];
            sc[a][2] = __expf(sc[a][2] - mn1); s1 += sc[a][2];
            sc[a][3] = __expf(sc[a][3] - mn1); s1 += sc[a][3];
        }
        s0 += __shfl_xor_sync(0xffffffffu, s0, 1);
        s0 += __shfl_xor_sync(0xffffffffu, s0, 2);
        s1 += __shfl_xor_sync(0xffffffffu, s1, 1);
        s1 += __shfl_xor_sync(0xffffffffu, s1, 2);
        l0 = l0 * c0 + s0;  l1 = l1 * c1 + s1;
        m0 = mn0;  m1 = mn1;
        #pragma unroll
        for (int da = 0; da < 8; ++da) {
            o[da][0] *= c0; o[da][1] *= c0;
            o[da][2] *= c1; o[da][3] *= c1;
        }

        #pragma unroll
        for (int a = 0; a < 8; ++a) {
            const int cb = 8 * a + 2 * tg;
            Ps[g * 68 + cb]           = f2tf(sc[a][0]);
            Ps[g * 68 + cb + 1]       = f2tf(sc[a][1]);
            Ps[(g + 8) * 68 + cb]     = f2tf(sc[a][2]);
            Ps[(g + 8) * 68 + cb + 1] = f2tf(sc[a][3]);
        }
        __syncwarp();

        const uint32_t* Vb = VtB + buf * AT_KVW;
        #pragma unroll
        for (int s = 0; s < 8; ++s) {
            uint32_t a0 = Ps[g * 68 + 8 * s + tg];
            uint32_t a1 = Ps[(g + 8) * 68 + 8 * s + tg];
            uint32_t a2 = Ps[g * 68 + 8 * s + tg + 4];
            uint32_t a3 = Ps[(g + 8) * 68 + 8 * s + tg + 4];
            const int rk0 = (8 * s + tg) * 72;
            const int rk1 = (8 * s + tg + 4) * 72;
            #pragma unroll
            for (int da = 0; da < 8; ++da) {
                uint32_t b0 = Vb[rk0 + 8 * da + g];
                uint32_t b1 = Vb[rk1 + 8 * da + g];
                mma_tf32(o[da], a0, a1, a2, a3, b0, b1);
            }
        }

        if (kt + 1 < KVLEN / 64) {
            sttile(buf ^ 1);
            __syncthreads();
            buf ^= 1;
        }
    }

    const float inv0 = 1.f / l0, inv1 = 1.f / l1;
    uint32_t* o0 = out + (size_t)(b * SQ + row0 + g) * DMODEL + h * DH;
    uint32_t* o1 = o0 + 8 * DMODEL;
    #pragma unroll
    for (int da = 0; da < 8; ++da) {
        const int col = 8 * da + 2 * tg;
        *(uint2*)&o0[col] = make_uint2(f2tf(o[da][0] * inv0), f2tf(o[da][1] * inv0));
        *(uint2*)&o1[col] = make_uint2(f2tf(o[da][2] * inv1), f2tf(o[da][3] * inv1));
    }
}

// ---------------- fused residual-add + LayerNorm (fp32 + tf32 outputs) ----------------
__launch_bounds__(256)
__global__ void ln_kernel(const float* __restrict__ resid, const float* __restrict__ y,
                          const float* __restrict__ gg, const float* __restrict__ bb,
                          float* __restrict__ outf, uint32_t* __restrict__ outt) {
    const int row = blockIdx.x, tid = threadIdx.x;
    __shared__ float redS[8], redS2[8];
    float4 rv = *(const float4*)(resid + (size_t)row * DMODEL + tid * 4);
    float4 yv = *(const float4*)(y     + (size_t)row * DMODEL + tid * 4);
    float v0 = rv.x + yv.x, v1 = rv.y + yv.y, v2 = rv.z + yv.z, v3 = rv.w + yv.w;
    float s  = v0 + v1 + v2 + v3;
    float s2 = v0 * v0 + v1 * v1 + v2 * v2 + v3 * v3;
    #pragma unroll
    for (int o = 16; o > 0; o >>= 1) {
        s  += __shfl_xor_sync(0xffffffffu, s,  o);
        s2 += __shfl_xor_sync(0xffffffffu, s2, o);
    }
    if ((tid & 31) == 0) { redS[tid >> 5] = s; redS2[tid >> 5] = s2; }
    __syncthreads();
    if (tid < 32) {
        float a  = (tid < 8) ? redS[tid]  : 0.f;
        float a2 = (tid < 8) ? redS2[tid] : 0.f;
        #pragma unroll
        for (int o = 4; o > 0; o >>= 1) {
            a  += __shfl_xor_sync(0xffffffffu, a,  o);
            a2 += __shfl_xor_sync(0xffffffffu, a2, o);
        }
        if (tid == 0) { redS[0] = a; redS2[0] = a2; }
    }
    __syncthreads();
    const float mean = redS[0] * (1.f / DMODEL);
    const float var  = redS2[0] * (1.f / DMODEL) - mean * mean;
    const float inv  = rsqrtf(var + 1e-5f);
    float4 gv = *(const float4*)(gg + tid * 4);
    float4 bv = *(const float4*)(bb + tid * 4);
    float4 o;
    o.x = (v0 - mean) * inv * gv.x + bv.x;
    o.y = (v1 - mean) * inv * gv.y + bv.y;
    o.z = (v2 - mean) * inv * gv.z + bv.z;
    o.w = (v3 - mean) * inv * gv.w + bv.w;
    *(float4*)(outf + (size_t)row * DMODEL + tid * 4) = o;
    *(uint4*)(outt + (size_t)row * DMODEL + tid * 4) =
        make_uint4(f2tf(o.x), f2tf(o.y), f2tf(o.z), f2tf(o.w));
}

// ---------------- launcher ----------------
extern "C" void kernel_launch(void* const* d_in, const int* in_sizes, int n_in,
                              void* d_out, int out_size) {
    const float* x      = (const float*)d_in[0];
    const int*   kvidx  = (const int*)d_in[3];
    const float* ptab   = (const float*)d_in[5];
    const float* Wq = (const float*)d_in[6];
    const float* bq = (const float*)d_in[7];
    const float* Wk = (const float*)d_in[8];
    const float* bk = (const float*)d_in[9];
    const float* Wv = (const float*)d_in[10];
    const float* bv = (const float*)d_in[11];
    const float* Wo = (const float*)d_in[12];
    const float* bo = (const float*)d_in[13];
    const float* ln1g = (const float*)d_in[14];
    const float* ln1b = (const float*)d_in[15];
    const float* W1 = (const float*)d_in[16];
    const float* b1 = (const float*)d_in[17];
    const float* W2 = (const float*)d_in[18];
    const float* b2 = (const float*)d_in[19];
    const float* ln2g = (const float*)d_in[20];
    const float* ln2b = (const float*)d_in[21];

    float *gx, *gqkv, *gt, *gbqkv;
    uint32_t *gxt, *ga, *gh, *gwt;
    cudaGetSymbolAddress((void**)&gx,    g_x);
    cudaGetSymbolAddress((void**)&gxt,   g_xt);
    cudaGetSymbolAddress((void**)&gqkv,  g_qkv);
    cudaGetSymbolAddress((void**)&ga,    g_attn);
    cudaGetSymbolAddress((void**)&gt,    g_tmp);
    cudaGetSymbolAddress((void**)&gh,    g_h);
    cudaGetSymbolAddress((void**)&gwt,   g_wt);
    cudaGetSymbolAddress((void**)&gbqkv, g_bqkv);

    cudaFuncSetAttribute((const void*)attn_tc,
                         cudaFuncAttributeMaxDynamicSharedMemorySize, ATTN_SMEM_BYTES);
    cudaFuncSetAttribute((const void*)gemm_tc<0, 0>,
                         cudaFuncAttributeMaxDynamicSharedMemorySize, GEMM_SMEM_BYTES);
    cudaFuncSetAttribute((const void*)gemm_tc<1, 1>,
                         cudaFuncAttributeMaxDynamicSharedMemorySize, GEMM_SMEM_BYTES);

    // ---- weight transpose+convert to [N][K] tf32 (once per call) ----
    {
        dim3 blk(32, 8);
        transp_tf<<<dim3(32, 32, TL), blk>>>(Wq, gwt + WQKV_OFF,
                                             1024, 1024, (size_t)1048576, (size_t)3145728);
        transp_tf<<<dim3(32, 32, TL), blk>>>(Wk, gwt + WQKV_OFF + 1024 * 1024,
                                             1024, 1024, (size_t)1048576, (size_t)3145728);
        transp_tf<<<dim3(32, 32, TL), blk>>>(Wv, gwt + WQKV_OFF + 2048 * 1024,
                                             1024, 1024, (size_t)1048576, (size_t)3145728);
        transp_tf<<<dim3(32, 32, TL), blk>>>(Wo, gwt + WO_OFF,
                                             1024, 1024, (size_t)1048576, (size_t)1048576);
        transp_tf<<<dim3(128, 32, TL), blk>>>(W1, gwt + W1_OFF,
                                              1024, 4096, (size_t)4194304, (size_t)4194304);
        transp_tf<<<dim3(32, 128, TL), blk>>>(W2, gwt + W2_OFF,
                                              4096, 1024, (size_t)4194304, (size_t)4194304);
        pack_qkv_b<<<(TL * QKVN + 255) / 256, 256>>>(bq, bk, bv, gbqkv, TL * QKVN);
    }

    const int n4 = NTOK * DMODEL / 4;
    conv_only<<<(n4 + 255) / 256, 256>>>((const float4*)x, (uint4*)gxt, n4);

    dim3 gQKV(QKVN / 128, NTOK / 128);     // (24, 32)
    dim3 gProj(DMODEL / 128, NTOK / 128);  // (8, 32)
    dim3 gF1(FFND / 128, NTOK / 128);      // (32, 32)
    dim3 gAttn(SQ / 128, NH, NB);          // (4, 16, 8)

    for (int l = 0; l < TL; ++l) {
        const uint32_t* Wqkv_l = gwt + WQKV_OFF + (size_t)l * DMODEL * QKVN;
        const uint32_t* Wo_l   = gwt + WO_OFF + (size_t)l * DMODEL * DMODEL;
        const uint32_t* W1_l   = gwt + W1_OFF + (size_t)l * DMODEL * FFND;
        const uint32_t* W2_l   = gwt + W2_OFF + (size_t)l * FFND * DMODEL;
        const float* ptab_l = ptab + (size_t)l * NUM_PAGES * 2 * PAGE * NH * DH;

        gemm_tc<0, 0><<<gQKV, 256, GEMM_SMEM_BYTES>>>(gxt, Wqkv_l, gbqkv + l * QKVN,
                                                      gqkv, nullptr, NTOK, QKVN, DMODEL);

        attn_tc<<<gAttn, 256, ATTN_SMEM_BYTES>>>(gqkv, ptab_l, kvidx, ga);

        gemm_tc<0, 0><<<gProj, 256, GEMM_SMEM_BYTES>>>(ga, Wo_l, bo + l * DMODEL,
                                                       gt, nullptr, NTOK, DMODEL, DMODEL);
        // layer-0 residual comes straight from the input tensor
        const float* resid1 = (l == 0) ? x : gx;
        ln_kernel<<<NTOK, 256>>>(resid1, gt, ln1g + l * DMODEL, ln1b + l * DMODEL, gx, gxt);

        gemm_tc<1, 1><<<gF1, 256, GEMM_SMEM_BYTES>>>(gxt, W1_l, b1 + l * FFND,
                                                     nullptr, gh, NTOK, FFND, DMODEL);
        gemm_tc<0, 0><<<gProj, 256, GEMM_SMEM_BYTES>>>(gh, W2_l, b2 + l * DMODEL,
                                                       gt, nullptr, NTOK, DMODEL, FFND);

        float* lnOut = (l == TL - 1) ? (float*)d_out : gx;
        ln_kernel<<<NTOK, 256>>>(gx, gt, ln2g + l * DMODEL, ln2b + l * DMODEL, lnOut, gxt);
    }
}

// round 15
// speedup vs baseline: 1.1057x; 1.0576x over previous
#include <cuda_runtime.h>
#include <math.h>
#include <stdint.h>

// ---------------- problem constants (fixed shapes) ----------------
#define TL      4
#define NB      8
#define SQ      512
#define DMODEL  1024
#define NH      16
#define DH      64
#define PAGE    16
#define PPS     80
#define CACHED_TOK 768
#define KVLEN   1280
#define NTOK    4096
#define FFND    4096
#define NUM_PAGES 640
#define QKVN    3072

// ---------------- device scratch ----------------
__device__ float    g_x[NTOK * DMODEL];
__device__ uint32_t g_xt[NTOK * DMODEL];        // tf32 copy of x
__device__ float    g_qkv[NTOK * QKVN];         // fused QKV output (fp32)
__device__ uint32_t g_attn[NTOK * DMODEL];      // attn out, tf32
__device__ float    g_tmp[NTOK * DMODEL];
__device__ uint32_t g_h[NTOK * FFND];           // FFN mid, tf32
__device__ uint32_t g_wt[50331648];             // all weights, tf32, TRANSPOSED [N][K]
__device__ float    g_bqkv[TL * QKVN];

// weight offsets inside g_wt (all [N][K])
#define WQKV_OFF 0u            // [L][3072][1024] packed Q|K|V rows
#define WO_OFF   12582912u     // [L][1024][1024]
#define W1_OFF   16777216u     // [L][4096][1024]
#define W2_OFF   33554432u     // [L][1024][4096]

// ---------------- helpers ----------------
__device__ __forceinline__ uint32_t f2tf(float x) {
    uint32_t r;
    asm("cvt.rna.tf32.f32 %0, %1;" : "=r"(r) : "f"(x));
    return r;
}

__device__ __forceinline__ void mma_tf32(float d[4],
                                         uint32_t a0, uint32_t a1, uint32_t a2, uint32_t a3,
                                         uint32_t b0, uint32_t b1) {
    asm volatile(
        "mma.sync.aligned.m16n8k8.row.col.f32.tf32.tf32.f32 "
        "{%0,%1,%2,%3}, {%4,%5,%6,%7}, {%8,%9}, {%0,%1,%2,%3};\n"
        : "+f"(d[0]), "+f"(d[1]), "+f"(d[2]), "+f"(d[3])
        : "r"(a0), "r"(a1), "r"(a2), "r"(a3), "r"(b0), "r"(b1));
}

__device__ __forceinline__ void ldsm_x4(uint32_t& r0, uint32_t& r1, uint32_t& r2, uint32_t& r3,
                                        uint32_t addr) {
    asm volatile("ldmatrix.sync.aligned.m8n8.x4.shared.b16 {%0,%1,%2,%3}, [%4];"
                 : "=r"(r0), "=r"(r1), "=r"(r2), "=r"(r3) : "r"(addr));
}

__device__ __forceinline__ void cp_async16(uint32_t smem_dst, const void* gsrc) {
    asm volatile("cp.async.ca.shared.global [%0], [%1], 16;\n" :: "r"(smem_dst), "l"(gsrc));
}
__device__ __forceinline__ void cp_commit() { asm volatile("cp.async.commit_group;\n"); }
template<int N>
__device__ __forceinline__ void cp_wait() { asm volatile("cp.async.wait_group %0;\n" :: "n"(N)); }

// ---------------- conversion / packing kernels ----------------
// fused transpose for the 4 projection matrices: grid.z = mat*TL + l,
// mat 0..2 -> packed QKV rows, mat 3 -> Wo. Each is [1024][1024] fp32 -> [N][K] tf32.
__global__ void transp_proj(const float* __restrict__ Wq, const float* __restrict__ Wk,
                            const float* __restrict__ Wv, const float* __restrict__ Wo,
                            uint32_t* __restrict__ gwt) {
    __shared__ float t[32][33];
    const int z = blockIdx.z;
    const int mat = z >> 2;          // 0..3
    const int l   = z & 3;           // layer
    const float* src = (mat == 0 ? Wq : mat == 1 ? Wk : mat == 2 ? Wv : Wo)
                     + (size_t)l * 1048576;
    uint32_t* dst = gwt + (mat < 3 ? (WQKV_OFF + (size_t)l * 3145728 + (size_t)mat * 1048576)
                                   : (WO_OFF + (size_t)l * 1048576));
    const int c0 = blockIdx.x * 32, r0 = blockIdx.y * 32;
    const int x = threadIdx.x, y = threadIdx.y;
    #pragma unroll
    for (int i = 0; i < 32; i += 8)
        t[y + i][x] = src[(size_t)(r0 + y + i) * 1024 + c0 + x];
    __syncthreads();
    #pragma unroll
    for (int i = 0; i < 32; i += 8)
        dst[(size_t)(c0 + y + i) * 1024 + r0 + x] = f2tf(t[x][y + i]);
}

// generic transpose src[R][C] fp32 -> dst[C][R] tf32, grid.z = layer (FFN weights)
__global__ void transp_tf(const float* __restrict__ src, uint32_t* __restrict__ dst,
                          int R, int C, size_t sS, size_t sD) {
    __shared__ float t[32][33];
    src += (size_t)blockIdx.z * sS;
    dst += (size_t)blockIdx.z * sD;
    const int c0 = blockIdx.x * 32, r0 = blockIdx.y * 32;
    const int x = threadIdx.x, y = threadIdx.y;
    #pragma unroll
    for (int i = 0; i < 32; i += 8)
        t[y + i][x] = src[(size_t)(r0 + y + i) * C + c0 + x];
    __syncthreads();
    #pragma unroll
    for (int i = 0; i < 32; i += 8)
        dst[(size_t)(c0 + y + i) * R + r0 + x] = f2tf(t[x][y + i]);
}

__global__ void pack_qkv_b(const float* __restrict__ bq, const float* __restrict__ bk,
                           const float* __restrict__ bv, float* __restrict__ dst, int n) {
    int i = blockIdx.x * blockDim.x + threadIdx.x;
    if (i >= n) return;
    const int l = i / QKVN, c = i % QKVN;
    float v;
    if (c < 1024)      v = bq[l * 1024 + c];
    else if (c < 2048) v = bk[l * 1024 + c - 1024];
    else               v = bv[l * 1024 + c - 2048];
    dst[i] = v;
}

__global__ void conv_only(const float4* __restrict__ src, uint4* __restrict__ dtf, int n4) {
    int i = blockIdx.x * blockDim.x + threadIdx.x;
    if (i < n4) {
        float4 v = src[i];
        dtf[i] = make_uint4(f2tf(v.x), f2tf(v.y), f2tf(v.z), f2tf(v.w));
    }
}

// ---------------- tf32 tensor-core GEMM: BK=32, 3-stage, ldmatrix fragments ----
// C[M,N] = A[M,K] @ Bt[N,K]^T + bias. Block 128x128, BK=32 (halves barrier
// count vs BK=16), 256 threads = 8 warps, warp tile 64x32, 4x4 m16n8k8.
// Smem per stage: A[128][36] + B[128][36] words; stride 36 -> LDSM banks
// (4r+k)%32 conflict-free; cp.async warp = 4 rows x 128B contiguous.
#define GSTAGES 3
#define TSTRIDE 36
#define TILE_WORDS (128 * TSTRIDE)            // 4608
#define STG_WORDS (2 * TILE_WORDS)            // 9216 words = 36KB
#define GEMM_SMEM_BYTES (GSTAGES * STG_WORDS * 4)   // 110592

template<int GELU, int OUTTF>
__launch_bounds__(256, 2)
__global__ void gemm_tc(const uint32_t* __restrict__ A, const uint32_t* __restrict__ Bt,
                        const float* __restrict__ bias,
                        float* __restrict__ Cf, uint32_t* __restrict__ Ct,
                        int M, int N, int K) {
    extern __shared__ uint32_t sm[];
    const uint32_t sbase = (uint32_t)__cvta_generic_to_shared(sm);

    const int tid  = threadIdx.x;
    const int lane = tid & 31;
    const int wid  = tid >> 5;
    const int wm   = wid & 1;
    const int wn   = wid >> 1;
    const int g    = lane >> 2;
    const int tg   = lane & 3;

    const int row0 = blockIdx.y * 128;
    const int col0 = blockIdx.x * 128;

    // cp.async mapping: chunk c (0..2047/stage) -> row=(c&1023)>>3, kq=c&7.
    // Per thread: 4 A rows + 4 B rows at baseRow+32i, kq fixed.
    const int baseRow = tid >> 3;        // 0..31
    const int kq      = tid & 7;         // 0..7

    const uint32_t* ApB = A  + (size_t)(row0 + baseRow) * K + kq * 4;
    const uint32_t* BpB = Bt + (size_t)(col0 + baseRow) * K + kq * 4;

    // ldmatrix lane addressing
    const int aRowL = wm * 64 + ((lane >> 3) & 1) * 8 + (lane & 7);
    const int aKL   = ((lane >> 4) & 1) * 4;
    const int bRowL = wn * 32 + ((lane >> 4) & 1) * 8 + (lane & 7);
    const int bKL   = ((lane >> 3) & 1) * 4;

    float acc[4][4][4];
    #pragma unroll
    for (int i = 0; i < 4; ++i)
        #pragma unroll
        for (int j = 0; j < 4; ++j)
            #pragma unroll
            for (int e = 0; e < 4; ++e) acc[i][j][e] = 0.f;

    const int nt = K >> 5;   // BK=32 chunks

    auto issue_cp = [&](int t) {
        const uint32_t sb = sbase + 4 * (t % GSTAGES) * STG_WORDS;
        #pragma unroll
        for (int i = 0; i < 4; ++i) {
            const int r = baseRow + 32 * i;
            cp_async16(sb + 4 * (r * TSTRIDE + kq * 4),
                       ApB + (size_t)(32 * i) * K + (size_t)t * 32);
            cp_async16(sb + 4 * (TILE_WORDS + r * TSTRIDE + kq * 4),
                       BpB + (size_t)(32 * i) * K + (size_t)t * 32);
        }
    };

    #pragma unroll
    for (int s = 0; s < GSTAGES - 1; ++s) { issue_cp(s); cp_commit(); }

    for (int t = 0; t < nt; ++t) {
        cp_wait<GSTAGES - 2>();
        __syncthreads();

        const uint32_t sb  = sbase + 4 * (t % GSTAGES) * STG_WORDS;
        const uint32_t Asb = sb;
        const uint32_t Bsb = sb + 4 * TILE_WORDS;

        #pragma unroll
        for (int ks = 0; ks < 4; ++ks) {
            const int k0 = ks * 8;
            uint32_t af[4][4], bf[4][2];
            #pragma unroll
            for (int mt = 0; mt < 4; ++mt)
                ldsm_x4(af[mt][0], af[mt][1], af[mt][2], af[mt][3],
                        Asb + 4 * ((aRowL + mt * 16) * TSTRIDE + k0 + aKL));
            #pragma unroll
            for (int op = 0; op < 2; ++op)
                ldsm_x4(bf[2 * op][0], bf[2 * op][1], bf[2 * op + 1][0], bf[2 * op + 1][1],
                        Bsb + 4 * ((bRowL + op * 16) * TSTRIDE + k0 + bKL));
            #pragma unroll
            for (int mt = 0; mt < 4; ++mt)
                #pragma unroll
                for (int j = 0; j < 4; ++j)
                    mma_tf32(acc[mt][j], af[mt][0], af[mt][1], af[mt][2], af[mt][3],
                             bf[j][0], bf[j][1]);
        }

        if (t + GSTAGES - 1 < nt) issue_cp(t + GSTAGES - 1);
        cp_commit();
    }

    // epilogue: bias (+ exact GELU), float2 stores
    #pragma unroll
    for (int j = 0; j < 4; ++j) {
        const int col = col0 + wn * 32 + j * 8 + 2 * tg;
        const float2 bb = *(const float2*)(bias + col);
        #pragma unroll
        for (int mt = 0; mt < 4; ++mt) {
            const int row = row0 + wm * 64 + mt * 16 + g;
            float2 lo, hi;
            lo.x = acc[mt][j][0] + bb.x;
            lo.y = acc[mt][j][1] + bb.y;
            hi.x = acc[mt][j][2] + bb.x;
            hi.y = acc[mt][j][3] + bb.y;
            if (GELU) {
                lo.x *= normcdff(lo.x); lo.y *= normcdff(lo.y);
                hi.x *= normcdff(hi.x); hi.y *= normcdff(hi.y);
            }
            if (OUTTF) {
                *(uint2*)(Ct + (size_t)row * N + col)       = make_uint2(f2tf(lo.x), f2tf(lo.y));
                *(uint2*)(Ct + (size_t)(row + 8) * N + col) = make_uint2(f2tf(hi.x), f2tf(hi.y));
            } else {
                *(float2*)(Cf + (size_t)row * N + col)       = lo;
                *(float2*)(Cf + (size_t)(row + 8) * N + col) = hi;
            }
        }
    }
}

// ---------------- tensor-core paged-KV flash attention (round-12 proven: occ 1) ----------------
#define AT_KVW (64 * 72)
#define AT_PSW (16 * 68)
#define ATTN_SMEM_BYTES ((4 * AT_KVW + 8 * AT_PSW) * 4)   // 108544

__launch_bounds__(256, 1)
__global__ void attn_tc(const float* __restrict__ qkv, const float* __restrict__ ptab,
                        const int* __restrict__ kvidx, uint32_t* __restrict__ out) {
    extern __shared__ uint32_t smA[];
    uint32_t* KtB = smA;                        // [2][64][72], swizzled [d][j]
    uint32_t* VtB = smA + 2 * AT_KVW;           // [2][64][72], [j][d]
    const int tid  = threadIdx.x;
    const int lane = tid & 31;
    const int wid  = tid >> 5;
    const int g    = lane >> 2;
    const int tg   = lane & 3;
    uint32_t* Ps = smA + 4 * AT_KVW + wid * AT_PSW;

    const int qt = blockIdx.x, h = blockIdx.y, b = blockIdx.z;
    const int row0 = qt * 128 + wid * 16;
    const float scale = 0.125f;

    uint32_t qf[8][4];
    {
        const float* q0 = qkv + (size_t)(b * SQ + row0 + g) * QKVN + h * DH;
        const float* q1 = q0 + 8 * QKVN;
        #pragma unroll
        for (int s = 0; s < 8; ++s) {
            qf[s][0] = f2tf(q0[8 * s + tg] * scale);
            qf[s][1] = f2tf(q1[8 * s + tg] * scale);
            qf[s][2] = f2tf(q0[8 * s + tg + 4] * scale);
            qf[s][3] = f2tf(q1[8 * s + tg + 4] * scale);
        }
    }

    float o[8][4];
    #pragma unroll
    for (int da = 0; da < 8; ++da)
        #pragma unroll
        for (int e = 0; e < 4; ++e) o[da][e] = 0.f;
    float m0 = -1e30f, m1 = -1e30f, l0 = 0.f, l1 = 0.f;

    float4 kst[4], vst[4];
    auto ldtile = [&](int kt) {
        #pragma unroll
        for (int r = 0; r < 4; ++r) {
            int c = tid + r * 256;
            int tok = c >> 4;
            int d4  = (c & 15) << 2;
            int kv = kt * 64 + tok;
            const float *kp, *vp;
            if (kv < CACHED_TOK) {
                int page = kvidx[b * PPS + (kv >> 4)];
                size_t base = (size_t)page * (2 * PAGE * NH * DH)
                            + (size_t)(kv & 15) * (NH * DH) + h * DH + d4;
                kp = ptab + base;
                vp = ptab + base + PAGE * NH * DH;
            } else {
                size_t off = (size_t)(b * SQ + (kv - CACHED_TOK)) * QKVN + h * DH + d4;
                kp = qkv + off + DMODEL;
                vp = qkv + off + 2 * DMODEL;
            }
            kst[r] = *(const float4*)kp;
            vst[r] = *(const float4*)vp;
        }
    };
    auto sttile = [&](int buf) {
        uint32_t* Kb = KtB + buf * AT_KVW;
        uint32_t* Vb = VtB + buf * AT_KVW;
        #pragma unroll
        for (int r = 0; r < 4; ++r) {
            int c = tid + r * 256;
            int tok = c >> 4;
            int d4  = (c & 15) << 2;
            int colp = tok ^ d4;
            Kb[(d4 + 0) * 72 + colp] = f2tf(kst[r].x);
            Kb[(d4 + 1) * 72 + colp] = f2tf(kst[r].y);
            Kb[(d4 + 2) * 72 + colp] = f2tf(kst[r].z);
            Kb[(d4 + 3) * 72 + colp] = f2tf(kst[r].w);
            *(uint4*)&Vb[tok * 72 + d4] =
                make_uint4(f2tf(vst[r].x), f2tf(vst[r].y), f2tf(vst[r].z), f2tf(vst[r].w));
        }
    };

    ldtile(0);
    sttile(0);
    __syncthreads();

    int buf = 0;
    for (int kt = 0; kt < KVLEN / 64; ++kt) {
        if (kt + 1 < KVLEN / 64) ldtile(kt + 1);

        const uint32_t* Kb = KtB + buf * AT_KVW;
        float sc[8][4];
        #pragma unroll
        for (int a = 0; a < 8; ++a)
            #pragma unroll
            for (int e = 0; e < 4; ++e) sc[a][e] = 0.f;
        #pragma unroll
        for (int s = 0; s < 8; ++s) {
            const uint32_t a0 = qf[s][0], a1 = qf[s][1], a2 = qf[s][2], a3 = qf[s][3];
            const int rk0 = (8 * s + tg) * 72;
            const int rk1 = (8 * s + tg + 4) * 72;
            #pragma unroll
            for (int a = 0; a < 8; ++a) {
                uint32_t b0 = Kb[rk0 + (8 * (a ^ s) + g)];
                uint32_t b1 = Kb[rk1 + (8 * (a ^ s) + (g ^ 4))];
                mma_tf32(sc[a], a0, a1, a2, a3, b0, b1);
            }
        }

        float mx0 = -1e30f, mx1 = -1e30f;
        #pragma unroll
        for (int a = 0; a < 8; ++a) {
            mx0 = fmaxf(mx0, fmaxf(sc[a][0], sc[a][1]));
            mx1 = fmaxf(mx1, fmaxf(sc[a][2], sc[a][3]));
        }
        mx0 = fmaxf(mx0, __shfl_xor_sync(0xffffffffu, mx0, 1));
        mx0 = fmaxf(mx0, __shfl_xor_sync(0xffffffffu, mx0, 2));
        mx1 = fmaxf(mx1, __shfl_xor_sync(0xffffffffu, mx1, 1));
        mx1 = fmaxf(mx1, __shfl_xor_sync(0xffffffffu, mx1, 2));
        const float mn0 = fmaxf(m0, mx0), mn1 = fmaxf(m1, mx1);
        const float c0 = __expf(m0 - mn0), c1 = __expf(m1 - mn1);
        float s0 = 0.f, s1 = 0.f;
        #pragma unroll
        for (int a = 0; a < 8; ++a) {
            sc[a][0] = __expf(sc[a][0] - mn0); s0 += sc[a][0];
            sc[a][1] = __expf(sc[a][1] - mn0); s0 += sc[a][1];
            sc[a][2] = __expf(sc[a][2] - mn1); s1 += sc[a][2];
            sc[a][3] = __expf(sc[a][3] - mn1); s1 += sc[a][3];
        }
        s0 += __shfl_xor_sync(0xffffffffu, s0, 1);
        s0 += __shfl_xor_sync(0xffffffffu, s0, 2);
        s1 += __shfl_xor_sync(0xffffffffu, s1, 1);
        s1 += __shfl_xor_sync(0xffffffffu, s1, 2);
        l0 = l0 * c0 + s0;  l1 = l1 * c1 + s1;
        m0 = mn0;  m1 = mn1;
        #pragma unroll
        for (int da = 0; da < 8; ++da) {
            o[da][0] *= c0; o[da][1] *= c0;
            o[da][2] *= c1; o[da][3] *= c1;
        }

        #pragma unroll
        for (int a = 0; a < 8; ++a) {
            const int cb = 8 * a + 2 * tg;
            Ps[g * 68 + cb]           = f2tf(sc[a][0]);
            Ps[g * 68 + cb + 1]       = f2tf(sc[a][1]);
            Ps[(g + 8) * 68 + cb]     = f2tf(sc[a][2]);
            Ps[(g + 8) * 68 + cb + 1] = f2tf(sc[a][3]);
        }
        __syncwarp();

        const uint32_t* Vb = VtB + buf * AT_KVW;
        #pragma unroll
        for (int s = 0; s < 8; ++s) {
            uint32_t a0 = Ps[g * 68 + 8 * s + tg];
            uint32_t a1 = Ps[(g + 8) * 68 + 8 * s + tg];
            uint32_t a2 = Ps[g * 68 + 8 * s + tg + 4];
            uint32_t a3 = Ps[(g + 8) * 68 + 8 * s + tg + 4];
            const int rk0 = (8 * s + tg) * 72;
            const int rk1 = (8 * s + tg + 4) * 72;
            #pragma unroll
            for (int da = 0; da < 8; ++da) {
                uint32_t b0 = Vb[rk0 + 8 * da + g];
                uint32_t b1 = Vb[rk1 + 8 * da + g];
                mma_tf32(o[da], a0, a1, a2, a3, b0, b1);
            }
        }

        if (kt + 1 < KVLEN / 64) {
            sttile(buf ^ 1);
            __syncthreads();
            buf ^= 1;
        }
    }

    const float inv0 = 1.f / l0, inv1 = 1.f / l1;
    uint32_t* o0 = out + (size_t)(b * SQ + row0 + g) * DMODEL + h * DH;
    uint32_t* o1 = o0 + 8 * DMODEL;
    #pragma unroll
    for (int da = 0; da < 8; ++da) {
        const int col = 8 * da + 2 * tg;
        *(uint2*)&o0[col] = make_uint2(f2tf(o[da][0] * inv0), f2tf(o[da][1] * inv0));
        *(uint2*)&o1[col] = make_uint2(f2tf(o[da][2] * inv1), f2tf(o[da][3] * inv1));
    }
}

// ---------------- fused residual-add + LayerNorm (fp32 + tf32 outputs) ----------------
__launch_bounds__(256)
__global__ void ln_kernel(const float* __restrict__ resid, const float* __restrict__ y,
                          const float* __restrict__ gg, const float* __restrict__ bb,
                          float* __restrict__ outf, uint32_t* __restrict__ outt) {
    const int row = blockIdx.x, tid = threadIdx.x;
    __shared__ float redS[8], redS2[8];
    float4 rv = *(const float4*)(resid + (size_t)row * DMODEL + tid * 4);
    float4 yv = *(const float4*)(y     + (size_t)row * DMODEL + tid * 4);
    float v0 = rv.x + yv.x, v1 = rv.y + yv.y, v2 = rv.z + yv.z, v3 = rv.w + yv.w;
    float s  = v0 + v1 + v2 + v3;
    float s2 = v0 * v0 + v1 * v1 + v2 * v2 + v3 * v3;
    #pragma unroll
    for (int o = 16; o > 0; o >>= 1) {
        s  += __shfl_xor_sync(0xffffffffu, s,  o);
        s2 += __shfl_xor_sync(0xffffffffu, s2, o);
    }
    if ((tid & 31) == 0) { redS[tid >> 5] = s; redS2[tid >> 5] = s2; }
    __syncthreads();
    if (tid < 32) {
        float a  = (tid < 8) ? redS[tid]  : 0.f;
        float a2 = (tid < 8) ? redS2[tid] : 0.f;
        #pragma unroll
        for (int o = 4; o > 0; o >>= 1) {
            a  += __shfl_xor_sync(0xffffffffu, a,  o);
            a2 += __shfl_xor_sync(0xffffffffu, a2, o);
        }
        if (tid == 0) { redS[0] = a; redS2[0] = a2; }
    }
    __syncthreads();
    const float mean = redS[0] * (1.f / DMODEL);
    const float var  = redS2[0] * (1.f / DMODEL) - mean * mean;
    const float inv  = rsqrtf(var + 1e-5f);
    float4 gv = *(const float4*)(gg + tid * 4);
    float4 bv = *(const float4*)(bb + tid * 4);
    float4 o;
    o.x = (v0 - mean) * inv * gv.x + bv.x;
    o.y = (v1 - mean) * inv * gv.y + bv.y;
    o.z = (v2 - mean) * inv * gv.z + bv.z;
    o.w = (v3 - mean) * inv * gv.w + bv.w;
    *(float4*)(outf + (size_t)row * DMODEL + tid * 4) = o;
    *(uint4*)(outt + (size_t)row * DMODEL + tid * 4) =
        make_uint4(f2tf(o.x), f2tf(o.y), f2tf(o.z), f2tf(o.w));
}

// ---------------- launcher ----------------
extern "C" void kernel_launch(void* const* d_in, const int* in_sizes, int n_in,
                              void* d_out, int out_size) {
    const float* x      = (const float*)d_in[0];
    const int*   kvidx  = (const int*)d_in[3];
    const float* ptab   = (const float*)d_in[5];
    const float* Wq = (const float*)d_in[6];
    const float* bq = (const float*)d_in[7];
    const float* Wk = (const float*)d_in[8];
    const float* bk = (const float*)d_in[9];
    const float* Wv = (const float*)d_in[10];
    const float* bv = (const float*)d_in[11];
    const float* Wo = (const float*)d_in[12];
    const float* bo = (const float*)d_in[13];
    const float* ln1g = (const float*)d_in[14];
    const float* ln1b = (const float*)d_in[15];
    const float* W1 = (const float*)d_in[16];
    const float* b1 = (const float*)d_in[17];
    const float* W2 = (const float*)d_in[18];
    const float* b2 = (const float*)d_in[19];
    const float* ln2g = (const float*)d_in[20];
    const float* ln2b = (const float*)d_in[21];

    float *gx, *gqkv, *gt, *gbqkv;
    uint32_t *gxt, *ga, *gh, *gwt;
    cudaGetSymbolAddress((void**)&gx,    g_x);
    cudaGetSymbolAddress((void**)&gxt,   g_xt);
    cudaGetSymbolAddress((void**)&gqkv,  g_qkv);
    cudaGetSymbolAddress((void**)&ga,    g_attn);
    cudaGetSymbolAddress((void**)&gt,    g_tmp);
    cudaGetSymbolAddress((void**)&gh,    g_h);
    cudaGetSymbolAddress((void**)&gwt,   g_wt);
    cudaGetSymbolAddress((void**)&gbqkv, g_bqkv);

    cudaFuncSetAttribute((const void*)attn_tc,
                         cudaFuncAttributeMaxDynamicSharedMemorySize, ATTN_SMEM_BYTES);
    cudaFuncSetAttribute((const void*)gemm_tc<0, 0>,
                         cudaFuncAttributeMaxDynamicSharedMemorySize, GEMM_SMEM_BYTES);
    cudaFuncSetAttribute((const void*)gemm_tc<1, 1>,
                         cudaFuncAttributeMaxDynamicSharedMemorySize, GEMM_SMEM_BYTES);

    // ---- weight transpose+convert to [N][K] tf32 (once per call) ----
    {
        dim3 blk(32, 8);
        transp_proj<<<dim3(32, 32, 4 * TL), blk>>>(Wq, Wk, Wv, Wo, gwt);
        transp_tf<<<dim3(128, 32, TL), blk>>>(W1, gwt + W1_OFF,
                                              1024, 4096, (size_t)4194304, (size_t)4194304);
        transp_tf<<<dim3(32, 128, TL), blk>>>(W2, gwt + W2_OFF,
                                              4096, 1024, (size_t)4194304, (size_t)4194304);
        pack_qkv_b<<<(TL * QKVN + 255) / 256, 256>>>(bq, bk, bv, gbqkv, TL * QKVN);
    }

    const int n4 = NTOK * DMODEL / 4;
    conv_only<<<(n4 + 255) / 256, 256>>>((const float4*)x, (uint4*)gxt, n4);

    dim3 gQKV(QKVN / 128, NTOK / 128);     // (24, 32)
    dim3 gProj(DMODEL / 128, NTOK / 128);  // (8, 32)
    dim3 gF1(FFND / 128, NTOK / 128);      // (32, 32)
    dim3 gAttn(SQ / 128, NH, NB);          // (4, 16, 8)

    for (int l = 0; l < TL; ++l) {
        const uint32_t* Wqkv_l = gwt + WQKV_OFF + (size_t)l * DMODEL * QKVN;
        const uint32_t* Wo_l   = gwt + WO_OFF + (size_t)l * DMODEL * DMODEL;
        const uint32_t* W1_l   = gwt + W1_OFF + (size_t)l * DMODEL * FFND;
        const uint32_t* W2_l   = gwt + W2_OFF + (size_t)l * FFND * DMODEL;
        const float* ptab_l = ptab + (size_t)l * NUM_PAGES * 2 * PAGE * NH * DH;

        gemm_tc<0, 0><<<gQKV, 256, GEMM_SMEM_BYTES>>>(gxt, Wqkv_l, gbqkv + l * QKVN,
                                                      gqkv, nullptr, NTOK, QKVN, DMODEL);

        attn_tc<<<gAttn, 256, ATTN_SMEM_BYTES>>>(gqkv, ptab_l, kvidx, ga);

        gemm_tc<0, 0><<<gProj, 256, GEMM_SMEM_BYTES>>>(ga, Wo_l, bo + l * DMODEL,
                                                       gt, nullptr, NTOK, DMODEL, DMODEL);
        // layer-0 residual comes straight from the input tensor
        const float* resid1 = (l == 0) ? x : gx;
        ln_kernel<<<NTOK, 256>>>(resid1, gt, ln1g + l * DMODEL, ln1b + l * DMODEL, gx, gxt);

        gemm_tc<1, 1><<<gF1, 256, GEMM_SMEM_BYTES>>>(gxt, W1_l, b1 + l * FFND,
                                                     nullptr, gh, NTOK, FFND, DMODEL);
        gemm_tc<0, 0><<<gProj, 256, GEMM_SMEM_BYTES>>>(gh, W2_l, b2 + l * DMODEL,
                                                       gt, nullptr, NTOK, DMODEL, FFND);

        float* lnOut = (l == TL - 1) ? (float*)d_out : gx;
        ln_kernel<<<NTOK, 256>>>(gx, gt, ln2g + l * DMODEL, ln2b + l * DMODEL, lnOut, gxt);
    }
}